// round 1
// baseline (speedup 1.0000x reference)
#include <cuda_runtime.h>
#include <cuda_bf16.h>
#include <cstdint>

#define DD 128      // feature dim
#define TM 128      // M tile (rows of G per CTA)
#define TK 64       // K tile (cols of G per iteration)
#define NTHREADS 256
#define NSPLIT 4    // K-slabs; grid = (m/TM)*NSPLIT

// ---- device scratch (no allocations allowed) ----
__device__ double g_acc;
__device__ float g_a[4096];                    // ||sub_x_i||^2
__device__ float g_b[8192];                    // ||all_x_j||^2
__device__ __align__(16) __nv_bfloat16 g_Yt[128 * 8192];  // all_x transposed, bf16: [d][n]

__global__ void zero_kernel() { g_acc = 0.0; }

// ---------------------------------------------------------------------------
// prep: per-row sumsq for sub_x (-> g_a) and all_x (-> g_b), plus bf16
// transposed copy of all_x into g_Yt[d][n]. One block = 32 rows.
// ---------------------------------------------------------------------------
__global__ void prep_kernel(const float* __restrict__ subx,
                            const float* __restrict__ allx, int m, int n) {
    __shared__ float ys[32 * 132];
    int b = blockIdx.x;
    int t = threadIdx.x;
    int nb_y = n / 32;
    bool isY = b < nb_y;
    const float* src = isY ? allx : subx;
    int r0 = isY ? b * 32 : (b - nb_y) * 32;

    // load 32x128 fp32 into smem (padded stride 132)
#pragma unroll
    for (int i = 0; i < 4; i++) {
        int ci = i * 256 + t;
        int rl = ci >> 5, c4 = ci & 31;
        float4 v = *(const float4*)(src + (size_t)(r0 + rl) * DD + c4 * 4);
        *(float4*)(ys + rl * 132 + c4 * 4) = v;
    }
    __syncthreads();

    // sumsq: 8 threads per row, 16 elems each, shfl-reduce width 8
    {
        int rl = t >> 3, sub = t & 7;
        const float* row = ys + rl * 132 + sub * 16;
        float s = 0.f;
#pragma unroll
        for (int i = 0; i < 16; i++) { float v = row[i]; s += v * v; }
        s += __shfl_down_sync(0xffffffffu, s, 4, 8);
        s += __shfl_down_sync(0xffffffffu, s, 2, 8);
        s += __shfl_down_sync(0xffffffffu, s, 1, 8);
        if (sub == 0) { if (isY) g_b[r0 + rl] = s; else g_a[r0 + rl] = s; }
    }

    if (isY) {
        // transposed bf16 write: thread t handles column d = t/2, 16 rows
        int d = t >> 1, half = t & 1;
        uint32_t pk[8];
#pragma unroll
        for (int i = 0; i < 8; i++) {
            int r = half * 16 + i * 2;
            float f0 = ys[r * 132 + d];
            float f1 = ys[(r + 1) * 132 + d];
            __nv_bfloat162 h = __float22bfloat162_rn(make_float2(f0, f1));
            pk[i] = *(uint32_t*)&h;
        }
        uint4* dst = (uint4*)(g_Yt + (size_t)d * n + r0 + half * 16);
        dst[0] = make_uint4(pk[0], pk[1], pk[2], pk[3]);
        dst[1] = make_uint4(pk[4], pk[5], pk[6], pk[7]);
    }
}

// ---------------------------------------------------------------------------
// main fused kernel
// ---------------------------------------------------------------------------
__device__ __forceinline__ void cpa16(void* smem_dst, const void* gsrc) {
    uint32_t s = (uint32_t)__cvta_generic_to_shared(smem_dst);
    asm volatile("cp.async.cg.shared.global [%0], [%1], 16;\n" ::"r"(s), "l"(gsrc));
}
__device__ __forceinline__ void cpa_commit() {
    asm volatile("cp.async.commit_group;\n" ::: "memory");
}
__device__ __forceinline__ uint32_t lds32(const __nv_bfloat16* p) {
    return *(const uint32_t*)p;
}

// smem layout constants (elements)
#define GST_STRIDE 68   // fp32 row stride (padded from 64)
#define BF_STRIDE  72   // bf16 row stride (padded from 64)

__global__ __launch_bounds__(NTHREADS, 1) void main_kernel(
    const float* __restrict__ G, const float* __restrict__ X, int m, int n) {
    extern __shared__ char smem[];
    float* Gst = (float*)smem;                                        // 3 * 128*68 fp32
    __nv_bfloat16* Yts = (__nv_bfloat16*)(smem + 3 * TM * GST_STRIDE * 4);  // 3 * 128*72
    __nv_bfloat16* Gbf = Yts + 3 * TM * BF_STRIDE;                    // 2 * 128*72
    float* a_s = (float*)(Gbf + 2 * TM * BF_STRIDE);                  // 128

    const int TILES = (n / NSPLIT) / TK;
    int t = threadIdx.x;
    int mt = blockIdx.x % (m / TM);
    int ks = blockIdx.x / (m / TM);
    int m0 = mt * TM;
    int k0 = ks * (n / NSPLIT);

    if (t < TM) a_s[t] = g_a[m0 + t];

    int lane = t & 31, w = t >> 5;
    int g = lane >> 2, tg = lane & 3;
    int mw = w * 16;

    float acc[16][4];
#pragma unroll
    for (int i = 0; i < 16; i++)
#pragma unroll
        for (int j = 0; j < 4; j++) acc[i][j] = 0.f;
    float s_deg = 0.f;

    // ---- issue one tile's loads into a stage ----
    auto issue_tile = [&](int stage, int tile) {
        int kk = k0 + tile * TK;
        float* gs = Gst + stage * (TM * GST_STRIDE);
#pragma unroll
        for (int i = 0; i < 8; i++) {
            int ci = i * NTHREADS + t;
            int r = ci >> 4, c = ci & 15;
            cpa16(gs + r * GST_STRIDE + c * 4, G + (size_t)(m0 + r) * n + kk + c * 4);
        }
        __nv_bfloat16* yv = Yts + stage * (TM * BF_STRIDE);
#pragma unroll
        for (int i = 0; i < 4; i++) {
            int ci = i * NTHREADS + t;
            int r = ci >> 3, c = ci & 7;
            cpa16(yv + r * BF_STRIDE + c * 8, g_Yt + (size_t)r * n + kk + c * 8);
        }
    };

    // prologue: tiles 0,1 into stages 0,1
    issue_tile(0, 0); cpa_commit();
    if (TILES > 1) issue_tile(1, 1);
    cpa_commit();

    for (int tile = 0; tile < TILES; tile++) {
        int s = tile % 3;
        int cb = tile & 1;
        asm volatile("cp.async.wait_group 1;\n" ::: "memory");
        __syncthreads();

        // ---- convert fp32 G -> bf16, accumulate deg terms (exact fp32 G) ----
        {
            float* gs = Gst + s * (TM * GST_STRIDE);
            __nv_bfloat16* gb = Gbf + cb * (TM * BF_STRIDE);
            int rb = t >> 3, ch = t & 7;
            int kk = k0 + tile * TK;
            float4 bA = *(const float4*)(g_b + kk + ch * 8);
            float4 bB = *(const float4*)(g_b + kk + ch * 8 + 4);
#pragma unroll
            for (int rr = 0; rr < 4; rr++) {
                int r = rb + rr * 32;
                const float4* p = (const float4*)(gs + r * GST_STRIDE + ch * 8);
                float4 v0 = p[0], v1 = p[1];
                float a_r = a_s[r];
                float sg = v0.x + v0.y + v0.z + v0.w + v1.x + v1.y + v1.z + v1.w;
                float db = v0.x * bA.x + v0.y * bA.y + v0.z * bA.z + v0.w * bA.w +
                           v1.x * bB.x + v1.y * bB.y + v1.z * bB.z + v1.w * bB.w;
                s_deg += a_r * sg + db;
                __nv_bfloat162 h0 = __float22bfloat162_rn(make_float2(v0.x, v0.y));
                __nv_bfloat162 h1 = __float22bfloat162_rn(make_float2(v0.z, v0.w));
                __nv_bfloat162 h2 = __float22bfloat162_rn(make_float2(v1.x, v1.y));
                __nv_bfloat162 h3 = __float22bfloat162_rn(make_float2(v1.z, v1.w));
                uint4 pk = make_uint4(*(uint32_t*)&h0, *(uint32_t*)&h1,
                                      *(uint32_t*)&h2, *(uint32_t*)&h3);
                *(uint4*)(gb + r * BF_STRIDE + ch * 8) = pk;
            }
        }
        __syncthreads();

        if (tile + 2 < TILES) issue_tile((tile + 2) % 3, tile + 2);
        cpa_commit();

        // ---- MMA: Z[128,128] += Gtile(128x64) * Ytile^T ----
        {
            __nv_bfloat16* gb = Gbf + cb * (TM * BF_STRIDE);
            __nv_bfloat16* yv = Yts + s * (TM * BF_STRIDE);
#pragma unroll
            for (int ksub = 0; ksub < 4; ksub++) {
                int kk = ksub * 16;
                uint32_t a0 = lds32(gb + (mw + g) * BF_STRIDE + kk + 2 * tg);
                uint32_t a1 = lds32(gb + (mw + g + 8) * BF_STRIDE + kk + 2 * tg);
                uint32_t a2 = lds32(gb + (mw + g) * BF_STRIDE + kk + 8 + 2 * tg);
                uint32_t a3 = lds32(gb + (mw + g + 8) * BF_STRIDE + kk + 8 + 2 * tg);
#pragma unroll
                for (int nt = 0; nt < 16; nt++) {
                    uint32_t b0 = lds32(yv + (nt * 8 + g) * BF_STRIDE + kk + 2 * tg);
                    uint32_t b1 = lds32(yv + (nt * 8 + g) * BF_STRIDE + kk + 8 + 2 * tg);
                    asm volatile(
                        "mma.sync.aligned.m16n8k16.row.col.f32.bf16.bf16.f32 "
                        "{%0,%1,%2,%3},{%4,%5,%6,%7},{%8,%9},{%0,%1,%2,%3};\n"
                        : "+f"(acc[nt][0]), "+f"(acc[nt][1]),
                          "+f"(acc[nt][2]), "+f"(acc[nt][3])
                        : "r"(a0), "r"(a1), "r"(a2), "r"(a3), "r"(b0), "r"(b1));
                }
            }
        }
    }

    // ---- epilogue: cross partial = sum Z .* sub_x over this CTA's tile ----
    float s_cross = 0.f;
#pragma unroll
    for (int nt = 0; nt < 16; nt++) {
        int d = nt * 8 + 2 * tg;
        const float* xp = X + (size_t)(m0 + mw + g) * DD + d;
        float2 x0 = *(const float2*)xp;
        float2 x1 = *(const float2*)(xp + 8 * DD);
        s_cross += acc[nt][0] * x0.x + acc[nt][1] * x0.y +
                   acc[nt][2] * x1.x + acc[nt][3] * x1.y;
    }
    float tot = s_deg - 2.f * s_cross;
#pragma unroll
    for (int o = 16; o > 0; o >>= 1) tot += __shfl_down_sync(0xffffffffu, tot, o);
    __shared__ float wsum[8];
    if (lane == 0) wsum[w] = tot;
    __syncthreads();
    if (t == 0) {
        float s = 0.f;
#pragma unroll
        for (int i = 0; i < 8; i++) s += wsum[i];
        atomicAdd(&g_acc, (double)s);
    }
}

__global__ void final_kernel(float* out, long long mn) {
    out[0] = (float)(g_acc / (double)mn);
}

extern "C" void kernel_launch(void* const* d_in, const int* in_sizes, int n_in,
                              void* d_out, int out_size) {
    const float* G = (const float*)d_in[0];   // sub_graph [m,n]
    const float* X = (const float*)d_in[1];   // sub_x [m,128]
    const float* Y = (const float*)d_in[2];   // all_x [n,128]
    int m = in_sizes[1] / DD;
    int n = in_sizes[2] / DD;

    size_t smem = (size_t)3 * TM * GST_STRIDE * 4   // G fp32 stages
                + (size_t)3 * TM * BF_STRIDE * 2    // Yt bf16 stages
                + (size_t)2 * TM * BF_STRIDE * 2    // G bf16 buffers
                + (size_t)TM * 4;                   // a_s
    cudaFuncSetAttribute(main_kernel, cudaFuncAttributeMaxDynamicSharedMemorySize,
                         (int)smem);

    zero_kernel<<<1, 1>>>();
    prep_kernel<<<(m + n) / 32, 256>>>(X, Y, m, n);
    main_kernel<<<(m / TM) * NSPLIT, NTHREADS, smem>>>(G, X, m, n);
    final_kernel<<<1, 1>>>((float*)d_out, (long long)m * n);
}

// round 3
// speedup vs baseline: 1.5047x; 1.5047x over previous
#include <cuda_runtime.h>
#include <cuda_bf16.h>
#include <cstdint>

#define DD 128      // feature dim
#define TM 128      // M tile (rows of G per CTA)
#define TK 64       // K tile (cols of G per iteration)
#define NTHREADS 256
#define NSPLIT 4    // K-slabs; grid = (m/TM)*NSPLIT = 128

// ---- device scratch (no allocations allowed) ----
__device__ double g_acc;
__device__ float g_a[4096];                    // ||sub_x_i||^2
__device__ float g_b[8192];                    // ||all_x_j||^2
__device__ __align__(16) __nv_bfloat16 g_Yt[128 * 8192];  // all_x^T bf16: [d][n]

// ---- dynamic smem layout (bytes) ----
#define YB_STAGE 16384                 // 128 rows * 128B (bf16 64 cols, swizzled)
#define GB_SIZE  16384                 // 128 rows * 128B bf16, swizzled
#define SM_Y     0                     // 3 stages
#define SM_G     (3 * YB_STAGE)        // 2 buffers
#define SM_WSUM  (SM_G + 2 * GB_SIZE)  // 8 floats
#define SMEM_TOTAL (SM_WSUM + 64)

// ---------------------------------------------------------------------------
static __device__ __forceinline__ uint32_t smem_u32(const void* p) {
    return (uint32_t)__cvta_generic_to_shared(p);
}
static __device__ __forceinline__ void cpa16(uint32_t smem_dst, const void* gsrc) {
    asm volatile("cp.async.cg.shared.global [%0], [%1], 16;\n" ::"r"(smem_dst), "l"(gsrc));
}
static __device__ __forceinline__ void cpa_commit() {
    asm volatile("cp.async.commit_group;\n" ::: "memory");
}
static __device__ __forceinline__ void ldsm_x4(uint32_t* r, uint32_t addr) {
    asm volatile("ldmatrix.sync.aligned.m8n8.x4.shared.b16 {%0,%1,%2,%3}, [%4];"
                 : "=r"(r[0]), "=r"(r[1]), "=r"(r[2]), "=r"(r[3]) : "r"(addr));
}

// ---------------------------------------------------------------------------
// prep: per-row sumsq for sub_x (-> g_a) and all_x (-> g_b), plus bf16
// transposed copy of all_x into g_Yt[d][n]. One block = 32 rows. Zeros g_acc.
// ---------------------------------------------------------------------------
__global__ void prep_kernel(const float* __restrict__ subx,
                            const float* __restrict__ allx, int m, int n) {
    __shared__ float ys[32 * 132];
    int b = blockIdx.x;
    int t = threadIdx.x;
    if (b == 0 && t == 0) g_acc = 0.0;
    int nb_y = n / 32;
    bool isY = b < nb_y;
    const float* src = isY ? allx : subx;
    int r0 = isY ? b * 32 : (b - nb_y) * 32;

#pragma unroll
    for (int i = 0; i < 4; i++) {
        int ci = i * 256 + t;
        int rl = ci >> 5, c4 = ci & 31;
        float4 v = *(const float4*)(src + (size_t)(r0 + rl) * DD + c4 * 4);
        *(float4*)(ys + rl * 132 + c4 * 4) = v;
    }
    __syncthreads();

    {
        int rl = t >> 3, sub = t & 7;
        const float* row = ys + rl * 132 + sub * 16;
        float s = 0.f;
#pragma unroll
        for (int i = 0; i < 16; i++) { float v = row[i]; s += v * v; }
        s += __shfl_down_sync(0xffffffffu, s, 4, 8);
        s += __shfl_down_sync(0xffffffffu, s, 2, 8);
        s += __shfl_down_sync(0xffffffffu, s, 1, 8);
        if (sub == 0) { if (isY) g_b[r0 + rl] = s; else g_a[r0 + rl] = s; }
    }

    if (isY) {
        int d = t >> 1, half = t & 1;
        uint32_t pk[8];
#pragma unroll
        for (int i = 0; i < 8; i++) {
            int r = half * 16 + i * 2;
            float f0 = ys[r * 132 + d];
            float f1 = ys[(r + 1) * 132 + d];
            __nv_bfloat162 h = __float22bfloat162_rn(make_float2(f0, f1));
            pk[i] = *(uint32_t*)&h;
        }
        uint4* dst = (uint4*)(g_Yt + (size_t)d * n + r0 + half * 16);
        dst[0] = make_uint4(pk[0], pk[1], pk[2], pk[3]);
        dst[1] = make_uint4(pk[4], pk[5], pk[6], pk[7]);
    }
}

// ---------------------------------------------------------------------------
// main fused kernel. Warp w = (qm, qn, kh): computes Z[qm*64+.., qn*64+..]
// partial over k-half kh of each 64-wide K tile. Z accumulated in registers,
// dotted with sub_x at the end (K-split partials just add into the scalar).
// ---------------------------------------------------------------------------
__global__ __launch_bounds__(NTHREADS, 1)
void main_kernel(const float* __restrict__ G, const float* __restrict__ X,
                 int m, int n) {
    extern __shared__ char smem[];
    const uint32_t sb = smem_u32(smem);
    const uint32_t sY = sb + SM_Y;
    const uint32_t sG = sb + SM_G;
    float* wsum = (float*)(smem + SM_WSUM);

    const int TILES = (n / NSPLIT) / TK;   // 32
    const int t = threadIdx.x;
    const int wid = t >> 5, lane = t & 31;
    const int g = lane >> 2, tg = lane & 3;
    const int qm = wid & 1, qn = (wid >> 1) & 1, kh = wid >> 2;
    const int kbase = kh * 32;             // bf16-element k offset within tile

    const int mt = blockIdx.x & 31;        // m/TM = 32
    const int ks = blockIdx.x >> 5;
    const int m0 = mt * TM;
    const int k0 = ks * (n / NSPLIT);

    // Gproc mapping: thread handles rows rb+32*rr (rr=0..3), k-chunk ch (8 floats)
    const int rb = t >> 3, ch = t & 7;
    float a_reg[4];
#pragma unroll
    for (int rr = 0; rr < 4; rr++) a_reg[rr] = g_a[m0 + rb + 32 * rr];

    float acc[4][8][4];
#pragma unroll
    for (int i = 0; i < 4; i++)
#pragma unroll
        for (int j = 0; j < 8; j++)
#pragma unroll
            for (int c = 0; c < 4; c++) acc[i][j][c] = 0.f;
    float s_deg = 0.f;

    // ---- Y tile issue (bf16, 128 rows x 128B, XOR-swizzled) ----
    auto issue_y = [&](int stage, int tile) {
        int kk = k0 + tile * TK;
        uint32_t yv = sY + stage * YB_STAGE;
#pragma unroll
        for (int i = 0; i < 4; i++) {
            int ci = i * NTHREADS + t;
            int r = ci >> 3, c = ci & 7;
            cpa16(yv + r * 128 + ((c ^ (r & 7)) << 4),
                  g_Yt + (size_t)r * n + kk + c * 8);
        }
    };

    // ---- G tile regs (one tile ahead) ----
    float4 gv[8];
    auto ldg_g = [&](int tile) {
        int kk = k0 + tile * TK;
#pragma unroll
        for (int rr = 0; rr < 4; rr++) {
            const float* p = G + (size_t)(m0 + rb + 32 * rr) * n + kk + ch * 8;
            gv[2 * rr] = *(const float4*)p;
            gv[2 * rr + 1] = *(const float4*)(p + 4);
        }
    };
    float4 bA, bB, nbA, nbB;
    auto ldg_b = [&](int tile, float4& oA, float4& oB) {
        int kk = k0 + tile * TK;
        oA = *(const float4*)(g_b + kk + ch * 8);
        oB = *(const float4*)(g_b + kk + ch * 8 + 4);
    };

    // prologue
    ldg_g(0);
    ldg_b(0, bA, bB);
    issue_y(0, 0); cpa_commit();
    issue_y(1, 1); cpa_commit();

    for (int tile = 0; tile < TILES; tile++) {
        uint32_t gbuf = sG + (tile & 1) * GB_SIZE;
        uint32_t ybuf = sY + (tile % 3) * YB_STAGE;

        // ---- G pass in registers: exact fp32 deg terms + bf16 STS ----
#pragma unroll
        for (int rr = 0; rr < 4; rr++) {
            float4 v0 = gv[2 * rr], v1 = gv[2 * rr + 1];
            float sg = v0.x + v0.y + v0.z + v0.w + v1.x + v1.y + v1.z + v1.w;
            float db = v0.x * bA.x + v0.y * bA.y + v0.z * bA.z + v0.w * bA.w +
                       v1.x * bB.x + v1.y * bB.y + v1.z * bB.z + v1.w * bB.w;
            s_deg += a_reg[rr] * sg + db;
            __nv_bfloat162 h0 = __float22bfloat162_rn(make_float2(v0.x, v0.y));
            __nv_bfloat162 h1 = __float22bfloat162_rn(make_float2(v0.z, v0.w));
            __nv_bfloat162 h2 = __float22bfloat162_rn(make_float2(v1.x, v1.y));
            __nv_bfloat162 h3 = __float22bfloat162_rn(make_float2(v1.z, v1.w));
            int r = rb + 32 * rr;
            uint32_t ad = gbuf + r * 128 + ((ch ^ (r & 7)) << 4);
            asm volatile("st.shared.v4.b32 [%0], {%1,%2,%3,%4};" ::"r"(ad),
                         "r"(*(uint32_t*)&h0), "r"(*(uint32_t*)&h1),
                         "r"(*(uint32_t*)&h2), "r"(*(uint32_t*)&h3));
        }

        // prefetch next tile's G + b into regs (hidden under MMA)
        if (tile + 1 < TILES) { ldg_g(tile + 1); ldg_b(tile + 1, nbA, nbB); }

        asm volatile("cp.async.wait_group 1;\n" ::: "memory");
        __syncthreads();

        if (tile + 2 < TILES) issue_y((tile + 2) % 3, tile + 2);
        cpa_commit();

        // ---- MMA: acc += Gbf[qm-half, k-half] * Y[qn-half]^T via ldmatrix ----
#pragma unroll
        for (int ksb = 0; ksb < 2; ksb++) {
            int kk16 = kbase + ksb * 16;
            int cb = kk16 >> 3;            // 16B chunk index of k-start
            uint32_t A[4][4];
#pragma unroll
            for (int ms = 0; ms < 4; ms++) {
                int r = qm * 64 + ms * 16 + (lane & 15);
                int c = cb + (lane >> 4);
                ldsm_x4(A[ms], gbuf + r * 128 + ((c ^ (r & 7)) << 4));
            }
            uint32_t B[8][2];
#pragma unroll
            for (int p = 0; p < 4; p++) {
                int r = qn * 64 + p * 16 + (lane & 7) + ((lane >> 4) << 3);
                int c = cb + ((lane >> 3) & 1);
                uint32_t mm[4];
                ldsm_x4(mm, ybuf + r * 128 + ((c ^ (r & 7)) << 4));
                B[2 * p][0] = mm[0]; B[2 * p][1] = mm[1];
                B[2 * p + 1][0] = mm[2]; B[2 * p + 1][1] = mm[3];
            }
#pragma unroll
            for (int ms = 0; ms < 4; ms++)
#pragma unroll
                for (int ns = 0; ns < 8; ns++) {
                    asm volatile(
                        "mma.sync.aligned.m16n8k16.row.col.f32.bf16.bf16.f32 "
                        "{%0,%1,%2,%3},{%4,%5,%6,%7},{%8,%9},{%0,%1,%2,%3};\n"
                        : "+f"(acc[ms][ns][0]), "+f"(acc[ms][ns][1]),
                          "+f"(acc[ms][ns][2]), "+f"(acc[ms][ns][3])
                        : "r"(A[ms][0]), "r"(A[ms][1]), "r"(A[ms][2]), "r"(A[ms][3]),
                          "r"(B[ns][0]), "r"(B[ns][1]));
                }
        }
        bA = nbA; bB = nbB;
    }

    // ---- epilogue: cross partial = sum Z .* sub_x ----
    float s_cross = 0.f;
#pragma unroll
    for (int ms = 0; ms < 4; ms++) {
        int r1 = m0 + qm * 64 + ms * 16 + g;
#pragma unroll
        for (int ns = 0; ns < 8; ns++) {
            int col = qn * 64 + ns * 8 + 2 * tg;
            float2 x0 = *(const float2*)(X + (size_t)r1 * DD + col);
            float2 x1 = *(const float2*)(X + (size_t)(r1 + 8) * DD + col);
            s_cross += acc[ms][ns][0] * x0.x + acc[ms][ns][1] * x0.y +
                       acc[ms][ns][2] * x1.x + acc[ms][ns][3] * x1.y;
        }
    }

    float tot = s_deg - 2.f * s_cross;
#pragma unroll
    for (int o = 16; o > 0; o >>= 1) tot += __shfl_down_sync(0xffffffffu, tot, o);
    if (lane == 0) wsum[wid] = tot;
    __syncthreads();
    if (t == 0) {
        float s = 0.f;
#pragma unroll
        for (int i = 0; i < 8; i++) s += wsum[i];
        atomicAdd(&g_acc, (double)s);
    }
}

__global__ void final_kernel(float* out, long long mn) {
    out[0] = (float)(g_acc / (double)mn);
}

extern "C" void kernel_launch(void* const* d_in, const int* in_sizes, int n_in,
                              void* d_out, int out_size) {
    const float* G = (const float*)d_in[0];   // sub_graph [m,n]
    const float* X = (const float*)d_in[1];   // sub_x [m,128]
    const float* Y = (const float*)d_in[2];   // all_x [n,128]
    int m = in_sizes[1] / DD;
    int n = in_sizes[2] / DD;

    cudaFuncSetAttribute(main_kernel, cudaFuncAttributeMaxDynamicSharedMemorySize,
                         SMEM_TOTAL);

    prep_kernel<<<(m + n) / 32, 256>>>(X, Y, m, n);
    main_kernel<<<(m / TM) * NSPLIT, NTHREADS, SMEM_TOTAL>>>(G, X, m, n);
    final_kernel<<<1, 1>>>((float*)d_out, (long long)m * n);
}